// round 3
// baseline (speedup 1.0000x reference)
#include <cuda_runtime.h>
#include <cstdint>

#define N_USERS 100000
#define N_ITEMS 60000
#define N_NODES 160000
#define D 64
#define D2 32              // D in float2 units
#define NNZ 1280000
#define EPS 0.1f
#define SCAN_BS 1024
#define NB_SCAN ((N_NODES + SCAN_BS - 1) / SCAN_BS)   // 157
#define RPW 4              // rows per warp

// ---------------- scratch (static device globals; no allocation) -------------
__device__ int   g_cnt[N_NODES];                 // zero-init; invariant: zero between calls
__device__ int   g_rowptr[N_NODES + 1];
__device__ int   g_cursor[N_NODES];
__device__ unsigned long long g_state[NB_SCAN];  // decoupled-lookback state
__device__ int2  g_edges[NNZ];                   // packed (col, val-bits)
__device__ float g_ego1[(size_t)N_NODES * D];    // output of layer 0
__device__ float g_ego2[(size_t)N_NODES * D];    // output of layer 1

// ---------------- histogram (block 0 also resets lookback state) -------------
__global__ void k_hist(const int* __restrict__ rows) {
    if (blockIdx.x == 0 && threadIdx.x < NB_SCAN) g_state[threadIdx.x] = 0ULL;
    int e = blockIdx.x * blockDim.x + threadIdx.x;
    if (e < NNZ) atomicAdd(&g_cnt[rows[e]], 1);
}

// ---------------- single-pass exclusive scan with decoupled lookback ---------
__global__ void k_scan() {
    __shared__ int wsum[32];
    __shared__ int s_running;
    const int bid  = blockIdx.x;
    const int i    = bid * SCAN_BS + threadIdx.x;
    const int lane = threadIdx.x & 31;
    const int wid  = threadIdx.x >> 5;

    int v = (i < N_NODES) ? g_cnt[i] : 0;
    if (i < N_NODES) g_cnt[i] = 0;               // restore invariant for next call

    int s = v;
    #pragma unroll
    for (int d = 1; d < 32; d <<= 1) {
        int t = __shfl_up_sync(0xffffffffu, s, d);
        if (lane >= d) s += t;
    }
    if (lane == 31) wsum[wid] = s;
    __syncthreads();
    if (wid == 0) {
        int ws = wsum[lane];
        #pragma unroll
        for (int d = 1; d < 32; d <<= 1) {
            int t = __shfl_up_sync(0xffffffffu, ws, d);
            if (lane >= d) ws += t;
        }
        wsum[lane] = ws;
    }
    __syncthreads();
    const int incl  = s + (wid ? wsum[wid - 1] : 0);
    const int total = wsum[31];

    if (threadIdx.x == 0) {
        unsigned long long pk = ((bid == 0) ? (2ULL << 32) : (1ULL << 32))
                                | (unsigned)total;
        __threadfence();
        atomicExch(&g_state[bid], pk);
        if (bid == 0) { s_running = 0; g_rowptr[N_NODES] = NNZ; }
    }

    if (wid == 0 && bid > 0) {
        int running = 0;
        int pb = bid - 1;
        while (true) {
            int idx = pb - lane;
            unsigned long long st = 0ULL;
            if (idx >= 0) {
                do {
                    st = *(volatile unsigned long long*)&g_state[idx];
                } while ((st >> 32) == 0ULL);
            }
            unsigned pm = __ballot_sync(0xffffffffu, (idx >= 0) && ((st >> 32) == 2ULL));
            int val = (idx >= 0) ? (int)(st & 0xffffffffULL) : 0;
            if (pm) {
                int fp = __ffs(pm) - 1;
                int contrib = (lane <= fp) ? val : 0;
                #pragma unroll
                for (int m = 16; m; m >>= 1) contrib += __shfl_xor_sync(0xffffffffu, contrib, m);
                running += contrib;
                break;
            } else {
                int contrib = val;
                #pragma unroll
                for (int m = 16; m; m >>= 1) contrib += __shfl_xor_sync(0xffffffffu, contrib, m);
                running += contrib;
                pb -= 32;
            }
        }
        if (lane == 0) {
            __threadfence();
            atomicExch(&g_state[bid], (2ULL << 32) | (unsigned)(total + running));
            s_running = running;
        }
    }
    __syncthreads();

    const int excl = incl - v + s_running;
    if (i < N_NODES) { g_rowptr[i] = excl; g_cursor[i] = excl; }
}

// ---------------- scatter COO -> CSR (packed edges) ---------------------------
__global__ void k_scatter(const int* __restrict__ rows,
                          const int* __restrict__ cols,
                          const float* __restrict__ vals) {
    int e = blockIdx.x * blockDim.x + threadIdx.x;
    if (e < NNZ) {
        int r = rows[e];
        int p = atomicAdd(&g_cursor[r], 1);
        g_edges[p] = make_int2(cols[e], __float_as_int(vals[e]));
    }
}

// ---------------- fused SpMM + noise-perturb + epilogue ----------------------
// RPW rows per warp, interleaved: 4 independent edge-load->gather chains in
// flight per warp. Lane owns 2 consecutive features (float2). Edge records are
// loaded uniformly (HW warp broadcast) instead of shfl.
template <int K>
__global__ void k_spmm(const float2* __restrict__ xu,
                       const float2* __restrict__ xi,
                       const float2* __restrict__ noise,   // offset to layer K
                       const float2* __restrict__ prevA,   // K==2: ego1
                       const float2* __restrict__ prevB,   // K==2: ego2
                       float2* __restrict__ yout,          // K==0/1
                       float2* __restrict__ out2)          // d_out as float2
{
    const int gw   = (blockIdx.x * blockDim.x + threadIdx.x) >> 5;
    const int lane = threadIdx.x & 31;
    const int r0   = gw * RPW;
    if (r0 >= N_NODES) return;       // N_NODES % RPW == 0, no partial groups

    // hoisted independent loads: row extents + noise (DRAM latency overlaps loop)
    int    s[RPW], e[RPW];
    float2 nk[RPW];
    #pragma unroll
    for (int i = 0; i < RPW; ++i) {
        s[i]  = __ldg(&g_rowptr[r0 + i]);
        e[i]  = __ldg(&g_rowptr[r0 + i + 1]);
        nk[i] = __ldcs(noise + (size_t)(r0 + i) * D2 + lane);
    }

    float2 acc[RPW];
    #pragma unroll
    for (int i = 0; i < RPW; ++i) acc[i] = make_float2(0.f, 0.f);

    // interleaved edge walk: up to RPW independent load chains per trip
    while ((s[0] < e[0]) | (s[1] < e[1]) | (s[2] < e[2]) | (s[3] < e[3])) {
        int2 q[RPW];
        bool a[RPW];
        #pragma unroll
        for (int i = 0; i < RPW; ++i) {
            a[i] = s[i] < e[i];
            if (a[i]) q[i] = __ldg(&g_edges[s[i]]);      // uniform -> warp broadcast
        }
        #pragma unroll
        for (int i = 0; i < RPW; ++i) {
            if (a[i]) {
                int   cc = q[i].x;
                float vv = __int_as_float(q[i].y);
                const float2* xr = (cc < N_USERS)
                    ? (xu + (size_t)cc * D2)
                    : (xi + (size_t)(cc - N_USERS) * D2);
                float2 t = __ldg(xr + lane);
                acc[i].x = fmaf(vv, t.x, acc[i].x);
                acc[i].y = fmaf(vv, t.y, acc[i].y);
                s[i]++;
            }
        }
    }

    // epilogue per row: noise perturbation + layer-specific output
    #pragma unroll
    for (int i = 0; i < RPW; ++i) {
        const size_t off = (size_t)(r0 + i) * D2 + lane;
        float ss = nk[i].x * nk[i].x + nk[i].y * nk[i].y;
        #pragma unroll
        for (int m = 16; m; m >>= 1) ss += __shfl_xor_sync(0xffffffffu, ss, m);
        float inv = EPS / fmaxf(sqrtf(ss), 1e-12f);
        float sx = (acc[i].x > 0.f) ? 1.f : ((acc[i].x < 0.f) ? -1.f : 0.f);
        float sy = (acc[i].y > 0.f) ? 1.f : ((acc[i].y < 0.f) ? -1.f : 0.f);
        acc[i].x += sx * nk[i].x * inv;
        acc[i].y += sy * nk[i].y * inv;

        if (K == 0) {
            yout[off] = acc[i];                                  // ego1
            __stcs(out2 + (size_t)N_NODES * D2 + off, acc[i]);   // CL region
        } else if (K == 1) {
            yout[off] = acc[i];                                  // ego2
        } else {
            float2 pa = __ldcs(prevA + off);                     // ego1: last use
            float2 pb = __ldg(prevB + off);                      // ego2: L2-hot
            const float third = 1.f / 3.f;
            float2 f = make_float2((pa.x + pb.x + acc[i].x) * third,
                                   (pa.y + pb.y + acc[i].y) * third);
            __stcs(out2 + off, f);                               // final region
        }
    }
}

// ---------------- launch ------------------------------------------------------
extern "C" void kernel_launch(void* const* d_in, const int* in_sizes, int n_in,
                              void* d_out, int out_size) {
    const float* user_emb = (const float*)d_in[0];
    const float* item_emb = (const float*)d_in[1];
    const float* adj_vals = (const float*)d_in[2];
    const float* noise    = (const float*)d_in[3];
    const int*   adj_rows = (const int*)d_in[4];
    const int*   adj_cols = (const int*)d_in[5];
    float2* out2 = (float2*)d_out;

    // --- build CSR from COO ---
    k_hist<<<NNZ / 256, 256>>>(adj_rows);
    k_scan<<<NB_SCAN, SCAN_BS>>>();
    k_scatter<<<NNZ / 256, 256>>>(adj_rows, adj_cols, adj_vals);

    static float2* ego1 = nullptr;
    static float2* ego2 = nullptr;
    if (!ego1) {
        void* p;
        cudaGetSymbolAddress(&p, g_ego1); ego1 = (float2*)p;
        cudaGetSymbolAddress(&p, g_ego2); ego2 = (float2*)p;
    }

    const float2* noise2 = (const float2*)noise;
    const int threads = 256;                                   // 8 warps/block
    const int nwarps  = N_NODES / RPW;                         // 40000
    const int blocks  = (nwarps * 32 + threads - 1) / threads; // 5000

    // layer 0: x = concat(user_emb, item_emb) via two base pointers
    k_spmm<0><<<blocks, threads>>>((const float2*)user_emb,
                                   (const float2*)item_emb,
                                   noise2,
                                   nullptr, nullptr, ego1, out2);
    // layer 1: x = ego1 (contiguous -> xi = xu + N_USERS*D2)
    k_spmm<1><<<blocks, threads>>>((const float2*)ego1,
                                   (const float2*)ego1 + (size_t)N_USERS * D2,
                                   noise2 + (size_t)1 * N_NODES * D2,
                                   nullptr, nullptr, ego2, out2);
    // layer 2: x = ego2; epilogue writes final = (ego1+ego2+ego3)/3
    k_spmm<2><<<blocks, threads>>>((const float2*)ego2,
                                   (const float2*)ego2 + (size_t)N_USERS * D2,
                                   noise2 + (size_t)2 * N_NODES * D2,
                                   (const float2*)ego1, (const float2*)ego2,
                                   nullptr, out2);
}

// round 4
// speedup vs baseline: 1.3280x; 1.3280x over previous
#include <cuda_runtime.h>
#include <cstdint>

#define N_USERS 100000
#define N_ITEMS 60000
#define N_NODES 160000
#define D 64
#define D2 32              // D in float2 units
#define NNZ 1280000
#define EPS 0.1f
#define SCAN_BS 1024
#define NB_SCAN ((N_NODES + SCAN_BS - 1) / SCAN_BS)   // 157

// ---------------- scratch (static device globals; no allocation) -------------
__device__ int   g_cnt[N_NODES];                 // zero-init; invariant: zero between calls
__device__ int   g_rowptr[N_NODES + 1];
__device__ int   g_cursor[N_NODES];
__device__ unsigned long long g_state[NB_SCAN];  // decoupled-lookback state
__device__ int2  g_edges[NNZ];                   // packed (col, val-bits)
__device__ float g_ego1[(size_t)N_NODES * D];    // output of layer 0
__device__ float g_ego2[(size_t)N_NODES * D];    // output of layer 1

// ---------------- histogram (block 0 also resets lookback state) -------------
__global__ void k_hist(const int* __restrict__ rows) {
    if (blockIdx.x == 0 && threadIdx.x < NB_SCAN) g_state[threadIdx.x] = 0ULL;
    int e = blockIdx.x * blockDim.x + threadIdx.x;
    if (e < NNZ) atomicAdd(&g_cnt[rows[e]], 1);
}

// ---------------- single-pass exclusive scan with decoupled lookback ---------
__global__ void k_scan() {
    __shared__ int wsum[32];
    __shared__ int s_running;
    const int bid  = blockIdx.x;
    const int i    = bid * SCAN_BS + threadIdx.x;
    const int lane = threadIdx.x & 31;
    const int wid  = threadIdx.x >> 5;

    int v = (i < N_NODES) ? g_cnt[i] : 0;
    if (i < N_NODES) g_cnt[i] = 0;               // restore invariant for next call

    int s = v;
    #pragma unroll
    for (int d = 1; d < 32; d <<= 1) {
        int t = __shfl_up_sync(0xffffffffu, s, d);
        if (lane >= d) s += t;
    }
    if (lane == 31) wsum[wid] = s;
    __syncthreads();
    if (wid == 0) {
        int ws = wsum[lane];
        #pragma unroll
        for (int d = 1; d < 32; d <<= 1) {
            int t = __shfl_up_sync(0xffffffffu, ws, d);
            if (lane >= d) ws += t;
        }
        wsum[lane] = ws;
    }
    __syncthreads();
    const int incl  = s + (wid ? wsum[wid - 1] : 0);
    const int total = wsum[31];

    if (threadIdx.x == 0) {
        unsigned long long pk = ((bid == 0) ? (2ULL << 32) : (1ULL << 32))
                                | (unsigned)total;
        __threadfence();
        atomicExch(&g_state[bid], pk);
        if (bid == 0) { s_running = 0; g_rowptr[N_NODES] = NNZ; }
    }

    if (wid == 0 && bid > 0) {
        int running = 0;
        int pb = bid - 1;
        while (true) {
            int idx = pb - lane;
            unsigned long long st = 0ULL;
            if (idx >= 0) {
                do {
                    st = *(volatile unsigned long long*)&g_state[idx];
                } while ((st >> 32) == 0ULL);
            }
            unsigned pm = __ballot_sync(0xffffffffu, (idx >= 0) && ((st >> 32) == 2ULL));
            int val = (idx >= 0) ? (int)(st & 0xffffffffULL) : 0;
            if (pm) {
                int fp = __ffs(pm) - 1;
                int contrib = (lane <= fp) ? val : 0;
                #pragma unroll
                for (int m = 16; m; m >>= 1) contrib += __shfl_xor_sync(0xffffffffu, contrib, m);
                running += contrib;
                break;
            } else {
                int contrib = val;
                #pragma unroll
                for (int m = 16; m; m >>= 1) contrib += __shfl_xor_sync(0xffffffffu, contrib, m);
                running += contrib;
                pb -= 32;
            }
        }
        if (lane == 0) {
            __threadfence();
            atomicExch(&g_state[bid], (2ULL << 32) | (unsigned)(total + running));
            s_running = running;
        }
    }
    __syncthreads();

    const int excl = incl - v + s_running;
    if (i < N_NODES) { g_rowptr[i] = excl; g_cursor[i] = excl; }
}

// ---------------- scatter COO -> CSR (packed edges) ---------------------------
__global__ void k_scatter(const int* __restrict__ rows,
                          const int* __restrict__ cols,
                          const float* __restrict__ vals) {
    int e = blockIdx.x * blockDim.x + threadIdx.x;
    if (e < NNZ) {
        int r = rows[e];
        int p = atomicAdd(&g_cursor[r], 1);
        g_edges[p] = make_int2(cols[e], __float_as_int(vals[e]));
    }
}

// ---------------- fused SpMM + noise-perturb + epilogue ----------------------
// One warp per row; lane owns a float2. Inner loop: UNGUARDED unroll-4 over
// edges. Edge records loaded uniformly (one L1 line -> warp broadcast), then
// 4 independent gathers in flight. Row base address = one select + one IMAD
// via pre-adjusted item pointer (xi_adj = xi - N_USERS*D2).
template <int K>
__global__ void __launch_bounds__(256, 6)
k_spmm(const float2* __restrict__ xu,
       const float2* __restrict__ xi_adj,          // xi - N_USERS*D2 (only formed)
       const float2* __restrict__ noise,           // offset to layer K
       const float2* __restrict__ prevA,           // K==2: ego1
       const float2* __restrict__ prevB,           // K==2: ego2
       float2* __restrict__ yout,                  // K==0/1
       float2* __restrict__ out2)                  // d_out as float2
{
    const int gw   = (blockIdx.x * blockDim.x + threadIdx.x) >> 5;
    const int lane = threadIdx.x & 31;
    if (gw >= N_NODES) return;

    // hoisted independent loads (overlap DRAM latency with the edge walk)
    const size_t off = (size_t)gw * D2 + lane;
    const float2 nk  = __ldcs(noise + off);
    int p   = __ldg(&g_rowptr[gw]);
    int end = __ldg(&g_rowptr[gw + 1]);

    float2 acc = make_float2(0.f, 0.f);

    // main: 4 edges per trip, no guards
    for (; p + 4 <= end; p += 4) {
        const int2 e0 = __ldg(&g_edges[p + 0]);
        const int2 e1 = __ldg(&g_edges[p + 1]);
        const int2 e2 = __ldg(&g_edges[p + 2]);
        const int2 e3 = __ldg(&g_edges[p + 3]);
        const float2* b0 = ((e0.x < N_USERS) ? xu : xi_adj) + (size_t)e0.x * D2;
        const float2* b1 = ((e1.x < N_USERS) ? xu : xi_adj) + (size_t)e1.x * D2;
        const float2* b2 = ((e2.x < N_USERS) ? xu : xi_adj) + (size_t)e2.x * D2;
        const float2* b3 = ((e3.x < N_USERS) ? xu : xi_adj) + (size_t)e3.x * D2;
        const float2 t0 = __ldg(b0 + lane);
        const float2 t1 = __ldg(b1 + lane);
        const float2 t2 = __ldg(b2 + lane);
        const float2 t3 = __ldg(b3 + lane);
        acc.x = fmaf(__int_as_float(e0.y), t0.x, acc.x);
        acc.y = fmaf(__int_as_float(e0.y), t0.y, acc.y);
        acc.x = fmaf(__int_as_float(e1.y), t1.x, acc.x);
        acc.y = fmaf(__int_as_float(e1.y), t1.y, acc.y);
        acc.x = fmaf(__int_as_float(e2.y), t2.x, acc.x);
        acc.y = fmaf(__int_as_float(e2.y), t2.y, acc.y);
        acc.x = fmaf(__int_as_float(e3.y), t3.x, acc.x);
        acc.y = fmaf(__int_as_float(e3.y), t3.y, acc.y);
    }
    // remainder: 0-3 edges
    for (; p < end; ++p) {
        const int2 e0 = __ldg(&g_edges[p]);
        const float2* b0 = ((e0.x < N_USERS) ? xu : xi_adj) + (size_t)e0.x * D2;
        const float2 t0 = __ldg(b0 + lane);
        acc.x = fmaf(__int_as_float(e0.y), t0.x, acc.x);
        acc.y = fmaf(__int_as_float(e0.y), t0.y, acc.y);
    }

    // noise perturbation: ego += sign(ego) * (n / max(||n||, 1e-12)) * EPS
    float ss = nk.x * nk.x + nk.y * nk.y;
    #pragma unroll
    for (int m = 16; m; m >>= 1) ss += __shfl_xor_sync(0xffffffffu, ss, m);
    const float inv = EPS / fmaxf(sqrtf(ss), 1e-12f);
    const float sx = (acc.x > 0.f) ? 1.f : ((acc.x < 0.f) ? -1.f : 0.f);
    const float sy = (acc.y > 0.f) ? 1.f : ((acc.y < 0.f) ? -1.f : 0.f);
    acc.x += sx * nk.x * inv;
    acc.y += sy * nk.y * inv;

    if (K == 0) {
        yout[off] = acc;                                    // ego1 (reused next layer)
        __stcs(out2 + (size_t)N_NODES * D2 + off, acc);     // CL region: stream out
    } else if (K == 1) {
        yout[off] = acc;                                    // ego2
    } else {
        const float2 pa = __ldcs(prevA + off);              // ego1: last use
        const float2 pb = __ldg(prevB + off);               // ego2: L2-hot
        const float third = 1.f / 3.f;
        float2 f = make_float2((pa.x + pb.x + acc.x) * third,
                               (pa.y + pb.y + acc.y) * third);
        __stcs(out2 + off, f);                              // final region: stream out
    }
}

// ---------------- launch ------------------------------------------------------
extern "C" void kernel_launch(void* const* d_in, const int* in_sizes, int n_in,
                              void* d_out, int out_size) {
    const float* user_emb = (const float*)d_in[0];
    const float* item_emb = (const float*)d_in[1];
    const float* adj_vals = (const float*)d_in[2];
    const float* noise    = (const float*)d_in[3];
    const int*   adj_rows = (const int*)d_in[4];
    const int*   adj_cols = (const int*)d_in[5];
    float2* out2 = (float2*)d_out;

    // --- build CSR from COO ---
    k_hist<<<NNZ / 256, 256>>>(adj_rows);
    k_scan<<<NB_SCAN, SCAN_BS>>>();
    k_scatter<<<NNZ / 256, 256>>>(adj_rows, adj_cols, adj_vals);

    static float2* ego1 = nullptr;
    static float2* ego2 = nullptr;
    if (!ego1) {
        void* p;
        cudaGetSymbolAddress(&p, g_ego1); ego1 = (float2*)p;
        cudaGetSymbolAddress(&p, g_ego2); ego2 = (float2*)p;
    }

    const float2* noise2 = (const float2*)noise;
    const int threads = 256;
    const int blocks  = (N_NODES * 32 + threads - 1) / threads;   // 20000

    // layer 0: split tables; xi_adj = item_emb - N_USERS*D2 (pointer only formed)
    k_spmm<0><<<blocks, threads>>>((const float2*)user_emb,
                                   (const float2*)item_emb - (size_t)N_USERS * D2,
                                   noise2,
                                   nullptr, nullptr, ego1, out2);
    // layer 1: x = ego1 contiguous -> xi_adj == xu
    k_spmm<1><<<blocks, threads>>>((const float2*)ego1,
                                   (const float2*)ego1,
                                   noise2 + (size_t)1 * N_NODES * D2,
                                   nullptr, nullptr, ego2, out2);
    // layer 2: x = ego2; epilogue writes final = (ego1+ego2+ego3)/3
    k_spmm<2><<<blocks, threads>>>((const float2*)ego2,
                                   (const float2*)ego2,
                                   noise2 + (size_t)2 * N_NODES * D2,
                                   (const float2*)ego1, (const float2*)ego2,
                                   nullptr, out2);
}